// round 3
// baseline (speedup 1.0000x reference)
#include <cuda_runtime.h>
#include <cuda_bf16.h>

// Bilateral filter 5x5, sigma_xy = sigma_z = 1, zero padding.
// X: [NC, 512, 512] fp32 (NC = 12), out same shape.
//
// R2 -> R3 change: expand the exp2 argument quadratically.
//   L*((p-c)^2 + d2k) = L*p^2 - 2Lc*p + (L*c^2 + L*d2k)
// Per-pixel precompute b = -2Lc and g[d2] for the 6 distinct d2 values;
// per tap: 2 FFMA (first with immediate multiplier, rt=1) + EX2 + FFMA + FADD.
// fma-pipe ops/tap: 5 -> 4, issued instrs/pixel ~170 -> ~140, pushing the
// kernel onto the MUFU(EX2) floor (~17.5us busy).

#define TX   32
#define TYW  8
#define KY   4
#define BY   (TYW*KY)
#define HALO 2
#define SW   (TX + 2*HALO)   // 36
#define SH   (BY + 2*HALO)   // 36

__global__ __launch_bounds__(TX * TYW)
void bilateral_kernel(const float* __restrict__ X, float* __restrict__ out)
{
    __shared__ float tile[SH][SW];

    const int H = 512, W = 512;
    const int z = blockIdx.z;
    const float* __restrict__ img = X + (size_t)z * H * W;

    const int gx0 = blockIdx.x * TX - HALO;
    const int gy0 = blockIdx.y * BY - HALO;

    const int tid = threadIdx.y * TX + threadIdx.x;
    #pragma unroll
    for (int i = tid; i < SH * SW; i += TX * TYW) {
        const int sy = i / SW;
        const int sx = i - sy * SW;
        const int gx = gx0 + sx;
        const int gy = gy0 + sy;
        float v = 0.0f;
        if ((unsigned)gx < (unsigned)W && (unsigned)gy < (unsigned)H)
            v = img[gy * W + gx];
        tile[sy][sx] = v;
    }
    __syncthreads();

    const int tx = threadIdx.x;
    const int ty = threadIdx.y;
    const int row0 = ty * KY;

    // L = -0.5 * log2(e)
    const float L = -0.72134752044448170f;

    // Rolling 5x5 window in registers.
    float w[5][5];
    #pragma unroll
    for (int i = 0; i < 5; i++)
        #pragma unroll
        for (int j = 0; j < 5; j++)
            w[i][j] = tile[row0 + i][tx + j];

    const int gx  = blockIdx.x * TX + tx;
    const int gy1 = blockIdx.y * BY + ty * KY;
    float* __restrict__ o = out + (size_t)z * H * W + gy1 * W + gx;

    #pragma unroll
    for (int r = 0; r < KY; r++) {
        if (r > 0) {
            #pragma unroll
            for (int j = 0; j < 5; j++)
                w[(r - 1) % 5][j] = tile[row0 + r + 4][tx + j];
        }

        const float c = w[(r + 2) % 5][2];

        // Per-pixel precompute: b = -2Lc, g[d2] = L*c^2 + L*d2.
        const float b  = (-2.0f * L) * c;          // FMUL-imm
        const float Lc2 = (c * c) * L;             // FMUL, FMUL-imm
        // distinct d2 values: 0,1,2,4,5,8  (index by d2, holes unused)
        float g0 = Lc2;
        float g1 = Lc2 + L * 1.0f;
        float g2 = Lc2 + L * 2.0f;
        float g4 = Lc2 + L * 4.0f;
        float g5 = Lc2 + L * 5.0f;
        float g8 = Lc2 + L * 8.0f;

        float num = 0.0f;
        float den = 0.0f;

        #pragma unroll
        for (int dy = 0; dy < 5; dy++) {
            #pragma unroll
            for (int dx = 0; dx < 5; dx++) {
                const float p = w[(r + dy) % 5][dx];
                const int d2 = (dy - 2) * (dy - 2) + (dx - 2) * (dx - 2);
                const float gk = (d2 == 0) ? g0 : (d2 == 1) ? g1 : (d2 == 2) ? g2
                               : (d2 == 4) ? g4 : (d2 == 5) ? g5 : g8;
                const float t   = fmaf(L, p, b);    // FFMA-imm (rt=1)
                const float arg = fmaf(p, t, gk);   // FFMA
                float s;
                asm("ex2.approx.ftz.f32 %0, %1;" : "=f"(s) : "f"(arg));
                num = fmaf(s, p, num);
                den += s;
            }
        }

        o[r * W] = __fdividef(num, den);
    }
}

extern "C" void kernel_launch(void* const* d_in, const int* in_sizes, int n_in,
                              void* d_out, int out_size)
{
    const float* X = (const float*)d_in[0];
    float* out = (float*)d_out;

    const int H = 512, W = 512;
    const int NC = in_sizes[0] / (H * W);   // 12 for (4,3,512,512)

    dim3 block(TX, TYW);
    dim3 grid(W / TX, H / BY, NC);
    bilateral_kernel<<<grid, block>>>(X, out);
}

// round 4
// speedup vs baseline: 1.1523x; 1.1523x over previous
#include <cuda_runtime.h>
#include <cuda_bf16.h>

// Bilateral filter 5x5, sigma_xy = sigma_z = 1, zero padding.
// X: [NC, 512, 512] fp32 (NC = 12), out same shape.
//
// R3 -> R4:
//  * center tap free (s=1 exactly)
//  * exp2(L*c^2) common factor cancels in num/den -> EX2 taps need only
//      t = fma(L,p,b); arg = fma(p,t, L*d2)   with L*d2 compile-time
//  * 8 outer taps (d2 in {5,8}) use degree-3 poly for e^{-u/2}, u in [0,1]
//    (abs err ~1.6e-5, weights <=0.082 -> ~1e-5 output error)
//  * tap-pairs processed with packed fma.rn.f32x2 (Blackwell 2x FP32)
// EX2/pixel: 25 -> 17 (16 taps + 1 renorm). fma-pipe cycles roughly halved.

#define TX   32
#define TYW  8
#define KY   4
#define BY   (TYW*KY)
#define HALO 2
#define SW   (TX + 2*HALO)   // 36
#define SH   (BY + 2*HALO)   // 36

typedef unsigned long long ull;

__device__ __forceinline__ ull pack2(float a, float b) {
    ull r; asm("mov.b64 %0, {%1, %2};" : "=l"(r) : "f"(a), "f"(b)); return r;
}
__device__ __forceinline__ void unpack2(ull v, float& a, float& b) {
    asm("mov.b64 {%0, %1}, %2;" : "=f"(a), "=f"(b) : "l"(v));
}
__device__ __forceinline__ ull fma2(ull a, ull b, ull c) {
    ull d; asm("fma.rn.f32x2 %0, %1, %2, %3;" : "=l"(d) : "l"(a), "l"(b), "l"(c)); return d;
}
__device__ __forceinline__ ull add2(ull a, ull b) {
    ull d; asm("add.rn.f32x2 %0, %1, %2;" : "=l"(d) : "l"(a), "l"(b)); return d;
}
__device__ __forceinline__ ull mul2(ull a, ull b) {
    ull d; asm("mul.rn.f32x2 %0, %1, %2;" : "=l"(d) : "l"(a), "l"(b)); return d;
}
__device__ __forceinline__ float ex2f(float a) {
    float s; asm("ex2.approx.ftz.f32 %0, %1;" : "=f"(s) : "f"(a)); return s;
}

// L = -0.5*log2(e)
#define LCONST (-0.72134752044448170f)
// degree-3 Chebyshev approx of e^{-u/2} on [0,1]
#define PK0 (0.99999770f)
#define PK1 (-0.49942563f)
#define PK2 (0.12219345f)
#define PK3 (-0.01622403f)
// spatial weights e^{-d2/2}
#define W5C (0.08208499862f)
#define W8C (0.01831563889f)

__global__ __launch_bounds__(TX * TYW)
void bilateral_kernel(const float* __restrict__ X, float* __restrict__ out)
{
    __shared__ float tile[SH][SW];

    const int H = 512, W = 512;
    const int z = blockIdx.z;
    const float* __restrict__ img = X + (size_t)z * H * W;

    const int gx0 = blockIdx.x * TX - HALO;
    const int gy0 = blockIdx.y * BY - HALO;

    const int tid = threadIdx.y * TX + threadIdx.x;
    #pragma unroll
    for (int i = tid; i < SH * SW; i += TX * TYW) {
        const int sy = i / SW;
        const int sx = i - sy * SW;
        const int gx = gx0 + sx;
        const int gy = gy0 + sy;
        float v = 0.0f;
        if ((unsigned)gx < (unsigned)W && (unsigned)gy < (unsigned)H)
            v = img[gy * W + gx];
        tile[sy][sx] = v;
    }
    __syncthreads();

    const int tx = threadIdx.x;
    const int ty = threadIdx.y;
    const int row0 = ty * KY;

    // Rolling 5x5 window in registers.
    float w[5][5];
    #pragma unroll
    for (int i = 0; i < 5; i++)
        #pragma unroll
        for (int j = 0; j < 5; j++)
            w[i][j] = tile[row0 + i][tx + j];

    const int gx  = blockIdx.x * TX + tx;
    const int gy1 = blockIdx.y * BY + ty * KY;
    float* __restrict__ o = out + (size_t)z * H * W + gy1 * W + gx;

    const ull L2c = pack2(LCONST, LCONST);

    #pragma unroll
    for (int r = 0; r < KY; r++) {
        if (r > 0) {
            #pragma unroll
            for (int j = 0; j < 5; j++)
                w[(r - 1) % 5][j] = tile[row0 + r + 4][tx + j];
        }

        const float c = w[(r + 2) % 5][2];
        const float b = (-2.0f * LCONST) * c;
        const ull b2  = pack2(b, b);
        const ull cn2 = pack2(-c, -c);
        // renormalization: E = exp2(-L*c^2) = e^{c^2/2}
        const float E = ex2f((-LCONST) * (c * c));

        ull nume = pack2(0.0f, 0.0f), dene = nume;
        ull nump = nume, denp = nume;

        // ---- 8 EX2 tap-pairs (16 taps): arg = L*p^2 + b*p + L*d2 ----
        #define EX2PAIR(AY,AX,BY_,BX,D2A,D2B)                                   \
        {                                                                        \
            const float pa = w[(r + (AY)) % 5][AX];                              \
            const float pb = w[(r + (BY_)) % 5][BX];                             \
            const ull p2 = pack2(pa, pb);                                        \
            const ull t2 = fma2(L2c, p2, b2);                                    \
            const ull a2 = fma2(p2, t2,                                          \
                                pack2(LCONST * (float)(D2A), LCONST * (float)(D2B))); \
            float a0, a1; unpack2(a2, a0, a1);                                   \
            const ull s2 = pack2(ex2f(a0), ex2f(a1));                            \
            nume = fma2(s2, p2, nume);                                           \
            dene = add2(dene, s2);                                               \
        }
        EX2PAIR(0,2, 4,2, 4,4)
        EX2PAIR(1,0, 1,4, 5,5)
        EX2PAIR(1,1, 1,3, 2,2)
        EX2PAIR(1,2, 3,2, 1,1)
        EX2PAIR(2,0, 2,4, 4,4)
        EX2PAIR(2,1, 2,3, 1,1)
        EX2PAIR(3,0, 3,4, 5,5)
        EX2PAIR(3,1, 3,3, 2,2)
        #undef EX2PAIR

        // ---- 4 poly tap-pairs (8 taps, d2 in {5,8}): s = Wd2*e^{-u/2} ----
        #define POLYPAIR(AY,AX,BY_,BX,WD)                                        \
        {                                                                        \
            const float pa = w[(r + (AY)) % 5][AX];                              \
            const float pb = w[(r + (BY_)) % 5][BX];                             \
            const ull p2 = pack2(pa, pb);                                        \
            const ull d2v = add2(p2, cn2);                                       \
            const ull u2 = mul2(d2v, d2v);                                       \
            ull s2 = fma2(u2, pack2((WD)*PK3, (WD)*PK3),                         \
                          pack2((WD)*PK2, (WD)*PK2));                            \
            s2 = fma2(u2, s2, pack2((WD)*PK1, (WD)*PK1));                        \
            s2 = fma2(u2, s2, pack2((WD)*PK0, (WD)*PK0));                        \
            nump = fma2(s2, p2, nump);                                           \
            denp = add2(denp, s2);                                               \
        }
        POLYPAIR(0,0, 0,4, W8C)
        POLYPAIR(4,0, 4,4, W8C)
        POLYPAIR(0,1, 0,3, W5C)
        POLYPAIR(4,1, 4,3, W5C)
        #undef POLYPAIR

        // ---- merge: poly side (+center, s=1) scaled by E ----
        float ne0, ne1, de0, de1, np0, np1, dp0, dp1;
        unpack2(nume, ne0, ne1);
        unpack2(dene, de0, de1);
        unpack2(nump, np0, np1);
        unpack2(denp, dp0, dp1);
        const float num = fmaf(E, (np0 + np1) + c,    ne0 + ne1);
        const float den = fmaf(E, (dp0 + dp1) + 1.0f, de0 + de1);

        o[r * W] = __fdividef(num, den);
    }
}

extern "C" void kernel_launch(void* const* d_in, const int* in_sizes, int n_in,
                              void* d_out, int out_size)
{
    const float* X = (const float*)d_in[0];
    float* out = (float*)d_out;

    const int H = 512, W = 512;
    const int NC = in_sizes[0] / (H * W);   // 12 for (4,3,512,512)

    dim3 block(TX, TYW);
    dim3 grid(W / TX, H / BY, NC);
    bilateral_kernel<<<grid, block>>>(X, out);
}